// round 12
// baseline (speedup 1.0000x reference)
#include <cuda_runtime.h>
#include <math.h>

#define HEIGHT 1024
#define WIDTH  2048
#define PPT 4      // pixels per thread (4 | 2048, float4 aligned) -- R9 shape
#define TPB 256

// Grid trig tables, filled each call by init kernel (deterministic).
__device__ float g_sth[HEIGHT];
__device__ float g_cth[HEIGHT];
__device__ float g_sph[WIDTH];
__device__ float g_cph[WIDTH];

// Replicate the reference grid EXACTLY at float32 granularity (unchanged from
// the passing R7-R11 kernels -- keeps atan2 branch-cut flips at zero):
//   theta = fl32( fl32(gx * fl32(pi/2)) + fl32(pi/2) ),  gx exact
//   phi   = fl32( gy * fl32(pi) ),                       gy exact
// sin/cos in double, rounded to float (<=1 ulp vs numpy float32).
__global__ void init_tables_kernel()
{
    const int i = blockIdx.x * blockDim.x + threadIdx.x;
    if (i < HEIGHT) {
        const float gx = -1.0f + (float)i * (2.0f / (float)HEIGHT);
        const float th = __fadd_rn(__fmul_rn(gx, 1.5707963267948966f),
                                   1.5707963267948966f);
        double s, c;
        sincos((double)th, &s, &c);
        g_sth[i] = (float)s;
        g_cth[i] = (float)c;
    } else if (i < HEIGHT + WIDTH) {
        const int j = i - HEIGHT;
        const float gy = -1.0f + (float)j * (2.0f / (float)WIDTH);
        const float ph = __fmul_rn(gy, 3.14159265358979323846f);
        double s, c;
        sincos((double)ph, &s, &c);
        g_sph[j] = (float)s;
        g_cph[j] = (float)c;
    }
}

__device__ __forceinline__ float fsqrt_approx(float x) {
    float r;
    asm("sqrt.approx.f32 %0, %1;" : "=f"(r) : "f"(x));
    return r;
}

__global__ void __launch_bounds__(TPB)
depth3dgrid_kernel(const float* __restrict__ depth,
                   const float* __restrict__ trans,
                   float* __restrict__ out)
{
    __shared__ float sT[16];
    const int b = blockIdx.y;
    if (threadIdx.x < 16) sT[threadIdx.x] = trans[b * 16 + threadIdx.x];
    __syncthreads();

    // 4 consecutive pixels, same row
    const int base = (blockIdx.x * TPB + threadIdx.x) * PPT;
    const int h  = base >> 11;          // / WIDTH
    const int w0 = base & (WIDTH - 1);  // % WIDTH

    const float s_th = g_sth[h];
    const float c_th = g_cth[h];

    // Row-constant hoist (identical values to R9)
    const float a0 = s_th * sT[0],  a1 = s_th * sT[1],  a2 = s_th * sT[2];
    const float b0 = s_th * sT[4],  b1 = s_th * sT[5],  b2 = s_th * sT[6];
    const float k0 = c_th * sT[8],  k1 = c_th * sT[9],  k2 = c_th * sT[10];
    const float T30 = sT[12], T31 = sT[13], T32 = sT[14];

    const float4 cpv = *(const float4*)&g_cph[w0];
    const float4 spv = *(const float4*)&g_sph[w0];
    const float4 dv  = *(const float4*)(depth + (size_t)b * (HEIGHT * WIDTH) + base);

    const float cpa[4] = {cpv.x, cpv.y, cpv.z, cpv.w};
    const float spa[4] = {spv.x, spv.y, spv.z, spv.w};
    const float dd[4]  = {dv.x,  dv.y,  dv.z,  dv.w};

    float res[8];
#pragma unroll
    for (int k = 0; k < 4; ++k) {
        const float cp = cpa[k], sp = spa[k], d = dd[k];

        // transform (bit-identical fma chain to R9 -- sign-critical)
        const float px = fmaf(d, fmaf(cp, a0, fmaf(sp, b0, k0)), T30);
        const float py = fmaf(d, fmaf(cp, a1, fmaf(sp, b1, k1)), T31);
        const float pz = fmaf(d, fmaf(cp, a2, fmaf(sp, b2, k2)), T32);

        // t = pz / (sqrt(s2) + 1e-4) via rsqrt + first-order expansion
        const float s2  = fmaf(px, px, fmaf(py, py, fmaf(pz, pz, 1e-30f)));
        const float ris = rsqrtf(s2);
        const float pr  = pz * ris;
        const float t   = fmaf(pr * ris, -1e-4f, pr);

        // theta = acos(t)*2/pi - 1, with 2/pi folded into the P3 coefficients:
        //   acos(|t|)*2/pi = sqrt(1-|t|) * P3'(|t|)   (A&S 4.4.45 scaled)
        //   v = P3'*sqrt(u) - 1  in [-1, 0];  theta = sign(t) applied via XOR
        const float xa = fabsf(t);
        float p = fmaf(xa, -0.0119235f, 0.0472755f);   // -0.0187293 * 2/pi
        p = fmaf(p, xa, -0.1350346f);                  // -0.2121144 * 2/pi
        p = fmaf(p, xa,  0.9999573f);                  //  1.5707288 * 2/pi
        const float sq = fsqrt_approx(fmaxf(1.0f - xa, 1e-30f));
        const float v  = fmaf(p, sq, -1.0f);           // <= 0
        const float theta_o = __int_as_float(__float_as_int(v) ^
                                 (__float_as_int(t) & 0x80000000));

        // phi = atan2(py, px)/pi, with 1/pi folded into the P9 coefficients;
        // quadrant fixes become 0.5-q and 1-q (select structure R9-identical)
        const float ax = fabsf(px), ay = fabsf(py);
        const float mx = fmaxf(fmaxf(ax, ay), 1e-37f);
        const float mn = fminf(ax, ay);
        const float a  = __fdividef(mn, mx);
        const float ss = a * a;
        float q = fmaf(ss, 0.00663209f, -0.02709852f); //  0.0208351/pi, -0.0851330/pi
        q = fmaf(q, ss,  0.05734683f);                 //  0.1801410/pi
        q = fmaf(q, ss, -0.10513979f);                 // -0.3302995/pi
        q = fmaf(q, ss,  0.31826722f);                 //  0.9998660/pi
        q = q * a;                                     // atan(mn/mx)/pi
        q = (ay > ax)   ? (0.5f - q) : q;
        q = (px < 0.0f) ? (1.0f - q) : q;
        const float phi_o = copysignf(q, py);

        res[2 * k]     = phi_o;    // channel 0 = phi
        res[2 * k + 1] = theta_o;  // channel 1 = theta
    }

    float4* optr = (float4*)(out + ((size_t)b * (HEIGHT * WIDTH) + base) * 2);
    optr[0] = make_float4(res[0], res[1], res[2], res[3]);
    optr[1] = make_float4(res[4], res[5], res[6], res[7]);
}

extern "C" void kernel_launch(void* const* d_in, const int* in_sizes, int n_in,
                              void* d_out, int out_size)
{
    const float* depth = (const float*)d_in[0];   // (4,1024,2048,1) f32
    const float* trans = (const float*)d_in[1];   // (4,4,4) f32
    float* out = (float*)d_out;                   // (4,1024,2048,2) f32

    init_tables_kernel<<<(HEIGHT + WIDTH + 127) / 128, 128>>>();

    dim3 grid(HEIGHT * WIDTH / (TPB * PPT), 4, 1); // (2048, 4)
    depth3dgrid_kernel<<<grid, TPB>>>(depth, trans, out);
}

// round 13
// speedup vs baseline: 1.1939x; 1.1939x over previous
#include <cuda_runtime.h>
#include <math.h>

#define HEIGHT 1024
#define WIDTH  2048
#define PPT 4      // pixels per thread (4 | 2048, float4 aligned) -- R9/R12 shape
#define TPB 256

// ---------------------------------------------------------------------------
// Compile-time trig tables (replaces the R7-R12 init kernel -> one graph node).
// Replicates the reference grid EXACTLY at float32 granularity:
//   theta = fl32( fl32(gx * fl32(pi/2)) + fl32(pi/2) ),  gx = -1 + 2i/1024 exact
//   phi   = fl32( gy * fl32(pi) ),                       gy = -1 + j/1024 exact
// sin/cos evaluated in constexpr double (Taylor + reflection, |err| ~1e-15),
// rounded to float -> matches the FP64-sincos tables of R7-R12 to <=1 ulp.
// ---------------------------------------------------------------------------
constexpr double PI_D = 3.141592653589793238462643383279502884;

constexpr double ksin0(double x) {           // |x| <= pi/2
    const double x2 = x * x;
    double t = x, s = x;
    for (int k = 1; k <= 13; ++k) {
        t *= -x2 / (double)((2 * k) * (2 * k + 1));
        s += t;
    }
    return s;
}
constexpr double kcos0(double x) {           // |x| <= pi/2
    const double x2 = x * x;
    double t = 1.0, s = 1.0;
    for (int k = 1; k <= 13; ++k) {
        t *= -x2 / (double)((2 * k - 1) * (2 * k));
        s += t;
    }
    return s;
}
constexpr double ksin(double x) {            // |x| <= pi
    const double ax = x < 0 ? -x : x;
    const double s  = (ax > PI_D * 0.5) ? ksin0(PI_D - ax) : ksin0(ax);
    return x < 0 ? -s : s;
}
constexpr double kcos(double x) {            // |x| <= pi
    const double ax = x < 0 ? -x : x;
    return (ax > PI_D * 0.5) ? -kcos0(PI_D - ax) : kcos0(ax);
}

struct Tables {
    alignas(16) float sth[HEIGHT];
    alignas(16) float cth[HEIGHT];
    alignas(16) float sph[WIDTH];
    alignas(16) float cph[WIDTH];
};

constexpr Tables make_tables() {
    Tables t{};
    for (int i = 0; i < HEIGHT; ++i) {
        const float gx = -1.0f + (float)i * (2.0f / (float)HEIGHT);   // exact
        const float pm = gx * 1.5707963267948966f;                    // fl32 mul
        const float th = pm + 1.5707963267948966f;                    // fl32 add
        t.sth[i] = (float)ksin((double)th);
        t.cth[i] = (float)kcos((double)th);
    }
    for (int j = 0; j < WIDTH; ++j) {
        const float gy = -1.0f + (float)j * (2.0f / (float)WIDTH);    // exact
        const float ph = gy * 3.14159265358979323846f;                // fl32 mul
        t.sph[j] = (float)ksin((double)ph);
        t.cph[j] = (float)kcos((double)ph);
    }
    return t;
}

__device__ constexpr Tables g_tables = make_tables();

// ---------------------------------------------------------------------------

__device__ __forceinline__ float fsqrt_approx(float x) {
    float r;
    asm("sqrt.approx.f32 %0, %1;" : "=f"(r) : "f"(x));
    return r;
}

__global__ void __launch_bounds__(TPB)
depth3dgrid_kernel(const float* __restrict__ depth,
                   const float* __restrict__ trans,
                   float* __restrict__ out)
{
    __shared__ float sT[16];
    const int b = blockIdx.y;
    if (threadIdx.x < 16) sT[threadIdx.x] = trans[b * 16 + threadIdx.x];
    __syncthreads();

    // 4 consecutive pixels, same row
    const int base = (blockIdx.x * TPB + threadIdx.x) * PPT;
    const int h  = base >> 11;          // / WIDTH
    const int w0 = base & (WIDTH - 1);  // % WIDTH

    const float s_th = g_tables.sth[h];
    const float c_th = g_tables.cth[h];

    // Row-constant hoist (identical values to R9/R12)
    const float a0 = s_th * sT[0],  a1 = s_th * sT[1],  a2 = s_th * sT[2];
    const float b0 = s_th * sT[4],  b1 = s_th * sT[5],  b2 = s_th * sT[6];
    const float k0 = c_th * sT[8],  k1 = c_th * sT[9],  k2 = c_th * sT[10];
    const float T30 = sT[12], T31 = sT[13], T32 = sT[14];

    const float4 cpv = *(const float4*)&g_tables.cph[w0];
    const float4 spv = *(const float4*)&g_tables.sph[w0];
    const float4 dv  = *(const float4*)(depth + (size_t)b * (HEIGHT * WIDTH) + base);

    const float cpa[4] = {cpv.x, cpv.y, cpv.z, cpv.w};
    const float spa[4] = {spv.x, spv.y, spv.z, spv.w};
    const float dd[4]  = {dv.x,  dv.y,  dv.z,  dv.w};

    float res[8];
#pragma unroll
    for (int k = 0; k < 4; ++k) {
        const float cp = cpa[k], sp = spa[k], d = dd[k];

        // transform (bit-identical fma chain to R9/R12 -- sign-critical)
        const float px = fmaf(d, fmaf(cp, a0, fmaf(sp, b0, k0)), T30);
        const float py = fmaf(d, fmaf(cp, a1, fmaf(sp, b1, k1)), T31);
        const float pz = fmaf(d, fmaf(cp, a2, fmaf(sp, b2, k2)), T32);

        // t = pz / (sqrt(s2) + 1e-4) via rsqrt + first-order expansion
        const float s2  = fmaf(px, px, fmaf(py, py, fmaf(pz, pz, 1e-30f)));
        const float ris = rsqrtf(s2);
        const float pr  = pz * ris;
        const float t   = fmaf(pr * ris, -1e-4f, pr);

        // theta = acos(t)*2/pi - 1, 2/pi folded into P3 coefficients;
        // sign applied via XOR on v = P3'*sqrt(1-|t|) - 1  (in [-1,0])
        const float xa = fabsf(t);
        float p = fmaf(xa, -0.0119235f, 0.0472755f);
        p = fmaf(p, xa, -0.1350346f);
        p = fmaf(p, xa,  0.9999573f);
        const float sq = fsqrt_approx(fmaxf(1.0f - xa, 1e-30f));
        const float v  = fmaf(p, sq, -1.0f);
        const float theta_o = __int_as_float(__float_as_int(v) ^
                                 (__float_as_int(t) & 0x80000000));

        // phi = atan2(py, px)/pi, 1/pi folded into P9 coefficients;
        // quadrant fixes 0.5-q / 1-q (select structure R9-identical)
        const float ax = fabsf(px), ay = fabsf(py);
        const float mx = fmaxf(fmaxf(ax, ay), 1e-37f);
        const float mn = fminf(ax, ay);
        const float a  = __fdividef(mn, mx);
        const float ss = a * a;
        float q = fmaf(ss, 0.00663209f, -0.02709852f);
        q = fmaf(q, ss,  0.05734683f);
        q = fmaf(q, ss, -0.10513979f);
        q = fmaf(q, ss,  0.31826722f);
        q = q * a;                                     // atan(mn/mx)/pi
        q = (ay > ax)   ? (0.5f - q) : q;
        q = (px < 0.0f) ? (1.0f - q) : q;
        const float phi_o = copysignf(q, py);

        res[2 * k]     = phi_o;    // channel 0 = phi
        res[2 * k + 1] = theta_o;  // channel 1 = theta
    }

    float4* optr = (float4*)(out + ((size_t)b * (HEIGHT * WIDTH) + base) * 2);
    optr[0] = make_float4(res[0], res[1], res[2], res[3]);
    optr[1] = make_float4(res[4], res[5], res[6], res[7]);
}

extern "C" void kernel_launch(void* const* d_in, const int* in_sizes, int n_in,
                              void* d_out, int out_size)
{
    const float* depth = (const float*)d_in[0];   // (4,1024,2048,1) f32
    const float* trans = (const float*)d_in[1];   // (4,4,4) f32
    float* out = (float*)d_out;                   // (4,1024,2048,2) f32

    dim3 grid(HEIGHT * WIDTH / (TPB * PPT), 4, 1); // (2048, 4)
    depth3dgrid_kernel<<<grid, TPB>>>(depth, trans, out);
}